// round 3
// baseline (speedup 1.0000x reference)
#include <cuda_runtime.h>
#include <math.h>

// Problem constants (fixed by the dataset instance)
#define Bsz   16384
#define Csz   2048
#define Ksz   200
#define NCsz  1000
#define SLOTS 32

// GEMM1 tiling
#define BM      64
#define BK      32
#define NP      224   // K (concept) dim padded 200 -> 224 = 32*7
#define S2      36    // padded k-stride in smem
#define THREADS 256

// GEMM2 tiling
#define TNO 128
#define RB  128

// ---------------- device scratch (no allocations allowed) ----------------
__device__ float g_proto[Ksz * Csz];         // normalized prototypes = c / max(||c||,1e-12)
__device__ float g_fcwT[Ksz * NCsz];         // fc_w transposed: [K][NC]
__device__ int   g_sidx[Bsz * SLOTS];        // per-row surviving indices (padded)
__device__ float g_sval[Bsz * SLOTS];        // per-row surviving LN'd values (padded)

// ---------------- normalize prototypes exactly like the reference ----------------
__global__ void k_norm_kernel(const float* __restrict__ concepts) {
    __shared__ float red[THREADS];
    __shared__ float nrm;
    int k = blockIdx.x;
    const float* row = concepts + (size_t)k * Csz;
    float s = 0.f;
    for (int c = threadIdx.x; c < Csz; c += THREADS) {
        float v = row[c];
        s = fmaf(v, v, s);
    }
    red[threadIdx.x] = s;
    __syncthreads();
    for (int off = THREADS / 2; off > 0; off >>= 1) {
        if (threadIdx.x < off) red[threadIdx.x] += red[threadIdx.x + off];
        __syncthreads();
    }
    if (threadIdx.x == 0) nrm = fmaxf(sqrtf(red[0]), 1e-12f);
    __syncthreads();
    float n = nrm;
    for (int c = threadIdx.x; c < Csz; c += THREADS)
        g_proto[(size_t)k * Csz + c] = row[c] / n;   // div.rn, matches F.normalize rounding
}

// ---------------- transpose fc_w [NC,K] -> [K,NC] ----------------
__global__ void k_tr_kernel(const float* __restrict__ fc_w) {
    int k = blockIdx.x;
    for (int n = threadIdx.x; n < NCsz; n += blockDim.x)
        g_fcwT[k * NCsz + n] = fc_w[n * Ksz + k];
}

// ---------------- fused GEMM1 + LayerNorm + top-k select ----------------
// Block: 64 rows x 200(pad 224) concept cols. Chunked accumulation (32-term
// chunks merged into the main accumulator) keeps rounding error ~6e-7 so the
// rank-19/20 boundary matches the reference's sort.
__global__ __launch_bounds__(THREADS, 2)
void k_main_kernel(const float* __restrict__ x,
                   const float* __restrict__ lnw,
                   const float* __restrict__ lnb,
                   const int*   __restrict__ dfi) {
    __shared__ float smem[(BM + NP) * S2];   // 10368 floats (reused as feat[32][200])
    float* sx = smem;                  // [BM][S2]
    float* sp = smem + BM * S2;        // [NP][S2]

    const int tid = threadIdx.x;
    const int tm  = tid & 7;           // rows {tm + 8*i}, i=0..7
    const int tn  = tid >> 3;          // 0..31, cols {tn*7 + j}, j=0..6
    const int bm0 = blockIdx.x * BM;

    // zero the padding concept rows (n = 200..223) once; never rewritten
    for (int q = tid; q < (NP - Ksz) * S2; q += THREADS)
        sp[Ksz * S2 + q] = 0.f;

    float acc[8][7];
    #pragma unroll
    for (int i = 0; i < 8; i++)
        #pragma unroll
        for (int j = 0; j < 7; j++) acc[i][j] = 0.f;

    const int lr = tid & 63;           // x-loader row
    const int lk = (tid >> 6) * 8;     // x-loader k-offset

    for (int k0 = 0; k0 < Csz; k0 += BK) {
        __syncthreads();
        // x tile: [64 rows][32 k]
        {
            const float4* p = reinterpret_cast<const float4*>(
                x + (size_t)(bm0 + lr) * Csz + k0 + lk);
            float4 v0 = p[0], v1 = p[1];
            float* d = sx + lr * S2 + lk;
            d[0] = v0.x; d[1] = v0.y; d[2] = v0.z; d[3] = v0.w;
            d[4] = v1.x; d[5] = v1.y; d[6] = v1.z; d[7] = v1.w;
        }
        // prototype tile: [200 rows][32 k]
        for (int q = tid; q < Ksz * (BK / 4); q += THREADS) {
            int n  = q >> 3;
            int k4 = (q & 7) * 4;
            float4 v = *reinterpret_cast<const float4*>(
                g_proto + (size_t)n * Csz + k0 + k4);
            float* d = sp + n * S2 + k4;
            d[0] = v.x; d[1] = v.y; d[2] = v.z; d[3] = v.w;
        }
        __syncthreads();

        // --- i-group 0 (rows tm+8i, i=0..3), fresh chunk accumulator ---
        {
            float accT[4][7];
            #pragma unroll
            for (int i = 0; i < 4; i++)
                #pragma unroll
                for (int j = 0; j < 7; j++) accT[i][j] = 0.f;
            #pragma unroll 8
            for (int kk = 0; kk < BK; kk++) {
                float a[4], b[7];
                #pragma unroll
                for (int i = 0; i < 4; i++) a[i] = sx[(tm + 8 * i) * S2 + kk];
                #pragma unroll
                for (int j = 0; j < 7; j++) b[j] = sp[(tn * 7 + j) * S2 + kk];
                #pragma unroll
                for (int i = 0; i < 4; i++)
                    #pragma unroll
                    for (int j = 0; j < 7; j++)
                        accT[i][j] = fmaf(a[i], b[j], accT[i][j]);
            }
            #pragma unroll
            for (int i = 0; i < 4; i++)
                #pragma unroll
                for (int j = 0; j < 7; j++) acc[i][j] += accT[i][j];
        }
        // --- i-group 1 (rows tm+8i, i=4..7) ---
        {
            float accT[4][7];
            #pragma unroll
            for (int i = 0; i < 4; i++)
                #pragma unroll
                for (int j = 0; j < 7; j++) accT[i][j] = 0.f;
            #pragma unroll 8
            for (int kk = 0; kk < BK; kk++) {
                float a[4], b[7];
                #pragma unroll
                for (int i = 0; i < 4; i++) a[i] = sx[(tm + 8 * (i + 4)) * S2 + kk];
                #pragma unroll
                for (int j = 0; j < 7; j++) b[j] = sp[(tn * 7 + j) * S2 + kk];
                #pragma unroll
                for (int i = 0; i < 4; i++)
                    #pragma unroll
                    for (int j = 0; j < 7; j++)
                        accT[i][j] = fmaf(a[i], b[j], accT[i][j]);
            }
            #pragma unroll
            for (int i = 0; i < 4; i++)
                #pragma unroll
                for (int j = 0; j < 7; j++) acc[i + 4][j] += accT[i][j];
        }
    }
    __syncthreads();

    // ---- epilogue: LayerNorm (two-pass var), top-k threshold, sparse emit ----
    const int lane = tid & 31;
    const int wid  = tid >> 5;
    const int fi   = *dfi;
    const int ktop = Ksz - fi;         // = 20: threshold is the ktop-th largest |v|

    float* feat = smem;                // [32][Ksz], reuses tile smem

    for (int ph = 0; ph < 2; ph++) {
        #pragma unroll
        for (int i = 4 * ph; i < 4 * ph + 4; i++) {
            int rloc = tm + 8 * i - 32 * ph;
            #pragma unroll
            for (int j = 0; j < 7; j++) {
                int n = tn * 7 + j;
                if (n < Ksz) feat[rloc * Ksz + n] = acc[i][j];
            }
        }
        __syncthreads();
        // one warp handles 4 rows
        for (int rr = 0; rr < 4; rr++) {
            int rloc = wid * 4 + rr;
            int row  = bm0 + 32 * ph + rloc;
            float f[7];
            float s1 = 0.f;
            #pragma unroll
            for (int j = 0; j < 7; j++) {
                int n = lane + 32 * j;
                float v = (n < Ksz) ? feat[rloc * Ksz + n] : 0.f;
                f[j] = v;
                s1 += v;
            }
            #pragma unroll
            for (int off = 16; off > 0; off >>= 1)
                s1 += __shfl_xor_sync(0xffffffffu, s1, off);
            float mu = s1 / (float)Ksz;            // division: matches XLA mean
            // two-pass variance (matches jnp.var lowering)
            float s2 = 0.f;
            #pragma unroll
            for (int j = 0; j < 7; j++) {
                int n = lane + 32 * j;
                if (n < Ksz) {
                    float d = f[j] - mu;
                    s2 = fmaf(d, d, s2);
                }
            }
            #pragma unroll
            for (int off = 16; off > 0; off >>= 1)
                s2 += __shfl_xor_sync(0xffffffffu, s2, off);
            float var  = s2 / (float)Ksz;
            float rstd = 1.f / sqrtf(var + 1e-5f);

            float v[7], av[7], sel[7];
            #pragma unroll
            for (int j = 0; j < 7; j++) {
                int n = lane + 32 * j;
                if (n < Ksz) {
                    float z = (f[j] - mu) * rstd * lnw[n] + lnb[n];
                    v[j] = z; av[j] = fabsf(z); sel[j] = av[j];
                } else { v[j] = 0.f; av[j] = -1.f; sel[j] = -1.f; }
            }
            // extract ktop maxima; last extracted = threshold t
            float t = 0.f;
            for (int it = 0; it < ktop; it++) {
                float lm = sel[0]; int lj = 0;
                #pragma unroll
                for (int j = 1; j < 7; j++) if (sel[j] > lm) { lm = sel[j]; lj = j; }
                float m = lm;
                #pragma unroll
                for (int off = 16; off > 0; off >>= 1)
                    m = fmaxf(m, __shfl_xor_sync(0xffffffffu, m, off));
                unsigned ball = __ballot_sync(0xffffffffu, lm == m);
                int leader = __ffs((int)ball) - 1;
                if (lane == leader) sel[lj] = -2.f;   // remove exactly one instance
                t = m;
            }
            // emit survivors (strictly |v| > t), ascending concept index
            int cnt = 0;
            #pragma unroll
            for (int j = 0; j < 7; j++) {
                bool pred = (av[j] - t > 0.f);
                unsigned msk = __ballot_sync(0xffffffffu, pred);
                if (pred) {
                    int pos = cnt + __popc(msk & ((1u << lane) - 1u));
                    g_sidx[(size_t)row * SLOTS + pos] = lane + 32 * j;
                    g_sval[(size_t)row * SLOTS + pos] = v[j];
                }
                cnt += __popc(msk);
            }
            if (lane == 0) {   // zero-pad so GEMM2 can run a fixed-length loop
                for (int p = cnt; p < ktop; p++) {
                    g_sidx[(size_t)row * SLOTS + p] = 0;
                    g_sval[(size_t)row * SLOTS + p] = 0.f;
                }
            }
        }
        __syncthreads();
    }
}

// ---------------- sparse GEMM2: out = (sum val * fc_wT[idx,:]) + fc_b ----------------
__global__ __launch_bounds__(TNO, 2)
void k_out_kernel(const float* __restrict__ fcb,
                  const int*   __restrict__ dfi,
                  float* __restrict__ out) {
    extern __shared__ float ws[];      // [Ksz][TNO]
    const int tid = threadIdx.x;
    const int n0  = blockIdx.y * TNO;
    const int col = n0 + tid;
    const bool valid = col < NCsz;

    for (int k = 0; k < Ksz; k++)
        ws[k * TNO + tid] = valid ? g_fcwT[k * NCsz + col] : 0.f;
    __syncthreads();

    const float bb  = valid ? fcb[col] : 0.f;
    const int ktop  = Ksz - *dfi;
    const int r0    = blockIdx.x * RB;

    for (int r = 0; r < RB; r += 4) {
        int row0 = r0 + r;
        const int*   ip0 = g_sidx + (size_t)(row0 + 0) * SLOTS;
        const float* vp0 = g_sval + (size_t)(row0 + 0) * SLOTS;
        const int*   ip1 = g_sidx + (size_t)(row0 + 1) * SLOTS;
        const float* vp1 = g_sval + (size_t)(row0 + 1) * SLOTS;
        const int*   ip2 = g_sidx + (size_t)(row0 + 2) * SLOTS;
        const float* vp2 = g_sval + (size_t)(row0 + 2) * SLOTS;
        const int*   ip3 = g_sidx + (size_t)(row0 + 3) * SLOTS;
        const float* vp3 = g_sval + (size_t)(row0 + 3) * SLOTS;
        float a0 = 0.f, a1 = 0.f, a2 = 0.f, a3 = 0.f;
        #pragma unroll 5
        for (int j = 0; j < ktop; j++) {
            a0 = fmaf(vp0[j], ws[ip0[j] * TNO + tid], a0);
            a1 = fmaf(vp1[j], ws[ip1[j] * TNO + tid], a1);
            a2 = fmaf(vp2[j], ws[ip2[j] * TNO + tid], a2);
            a3 = fmaf(vp3[j], ws[ip3[j] * TNO + tid], a3);
        }
        if (valid) {   // bias added at the end (matches cublas epilogue order)
            out[(size_t)(row0 + 0) * NCsz + col] = a0 + bb;
            out[(size_t)(row0 + 1) * NCsz + col] = a1 + bb;
            out[(size_t)(row0 + 2) * NCsz + col] = a2 + bb;
            out[(size_t)(row0 + 3) * NCsz + col] = a3 + bb;
        }
    }
}

// ---------------- launch ----------------
extern "C" void kernel_launch(void* const* d_in, const int* in_sizes, int n_in,
                              void* d_out, int out_size) {
    const float* x        = (const float*)d_in[0];
    const float* concepts = (const float*)d_in[1];
    const float* lnw      = (const float*)d_in[2];
    const float* lnb      = (const float*)d_in[3];
    const float* fcw      = (const float*)d_in[4];
    const float* fcb      = (const float*)d_in[5];
    const int*   dfi      = (const int*)d_in[6];
    float* out = (float*)d_out;

    cudaFuncSetAttribute(k_out_kernel,
                         cudaFuncAttributeMaxDynamicSharedMemorySize,
                         Ksz * TNO * (int)sizeof(float));

    k_norm_kernel<<<Ksz, THREADS>>>(concepts);
    k_tr_kernel<<<Ksz, 256>>>(fcw);
    k_main_kernel<<<Bsz / BM, THREADS>>>(x, lnw, lnb, dfi);
    dim3 g2(Bsz / RB, (NCsz + TNO - 1) / TNO);
    k_out_kernel<<<g2, TNO, Ksz * TNO * (int)sizeof(float)>>>(fcb, dfi, out);
}